// round 1
// baseline (speedup 1.0000x reference)
#include <cuda_runtime.h>

// Problem constants
// x: (8, 512, 32, 32) fp32, viewed as xr[8192][512] (pure reshape)
// proj_w: (512, 512), proj_b: (512)
// score_w: (512), score_b: (1)
// ln_w: (25), ln_b: (25)
// out: (8, 512, 28, 28) fp32

#define M_ROWS 8192
#define KDIM   512
#define ODIM   512
#define HH     28

// Scratch (no runtime allocation allowed)
__device__ float g_proj[M_ROWS * ODIM];   // 16 MB
__device__ float g_score[M_ROWS];

// ---------------- packed fp32x2 helpers (Blackwell FFMA2) ----------------
__device__ __forceinline__ unsigned long long pack2(float x, float y) {
    unsigned long long r;
    asm("mov.b64 %0, {%1, %2};" : "=l"(r) : "f"(x), "f"(y));
    return r;
}
__device__ __forceinline__ void unpack2(unsigned long long v, float& x, float& y) {
    asm("mov.b64 {%0, %1}, %2;" : "=f"(x), "=f"(y) : "l"(v));
}
__device__ __forceinline__ void ffma2(unsigned long long& d, unsigned long long a,
                                      unsigned long long b) {
    asm("fma.rn.f32x2 %0, %1, %2, %0;" : "+l"(d) : "l"(a), "l"(b));
}

// ---------------- GEMM: g_proj[m][n] = sum_k x[m][k]*W[n][k] + b[n] ----------------
// 128x128x16 tiles, 256 threads, 8x8 microtile as 2x2 quads (conflict-free LDS.128).
__global__ __launch_bounds__(256, 2) void gemm_kernel(const float* __restrict__ A,
                                                      const float* __restrict__ B,
                                                      const float* __restrict__ bias) {
    __shared__ __align__(16) float As[16][128];
    __shared__ __align__(16) float Bs[16][128];
    const int tid = threadIdx.x;
    const int bm = blockIdx.y * 128;
    const int bn = blockIdx.x * 128;
    // loader mapping: 128 rows x 16 k, float4 along k; 2 rows per thread
    const int lr = tid >> 2;          // 0..63
    const int lc = (tid & 3) << 2;    // 0,4,8,12
    // microtile mapping: quads at (tm, tm+64) x (tn, tn+64)
    const int tm = (tid >> 4) << 2;   // 0..60
    const int tn = (tid & 15) << 2;   // 0..60

    unsigned long long acc[8][4];
#pragma unroll
    for (int i = 0; i < 8; i++)
#pragma unroll
        for (int j = 0; j < 4; j++) acc[i][j] = 0ULL;

    for (int k0 = 0; k0 < KDIM; k0 += 16) {
#pragma unroll
        for (int i = 0; i < 2; i++) {
            int r = lr + i * 64;
            float4 va = *(const float4*)&A[(size_t)(bm + r) * KDIM + k0 + lc];
            As[lc + 0][r] = va.x; As[lc + 1][r] = va.y;
            As[lc + 2][r] = va.z; As[lc + 3][r] = va.w;
            float4 vb = *(const float4*)&B[(size_t)(bn + r) * KDIM + k0 + lc];
            Bs[lc + 0][r] = vb.x; Bs[lc + 1][r] = vb.y;
            Bs[lc + 2][r] = vb.z; Bs[lc + 3][r] = vb.w;
        }
        __syncthreads();
#pragma unroll
        for (int kk = 0; kk < 16; kk++) {
            float4 a0 = *(const float4*)&As[kk][tm];
            float4 a1 = *(const float4*)&As[kk][tm + 64];
            ulonglong2 b0 = *(const ulonglong2*)&Bs[kk][tn];
            ulonglong2 b1 = *(const ulonglong2*)&Bs[kk][tn + 64];
            unsigned long long bp0 = b0.x, bp1 = b0.y, bp2 = b1.x, bp3 = b1.y;
            float av[8] = {a0.x, a0.y, a0.z, a0.w, a1.x, a1.y, a1.z, a1.w};
#pragma unroll
            for (int i = 0; i < 8; i++) {
                unsigned long long ap = pack2(av[i], av[i]);
                ffma2(acc[i][0], ap, bp0);
                ffma2(acc[i][1], ap, bp1);
                ffma2(acc[i][2], ap, bp2);
                ffma2(acc[i][3], ap, bp3);
            }
        }
        __syncthreads();
    }

    float4 bb0 = *(const float4*)&bias[bn + tn];
    float4 bb1 = *(const float4*)&bias[bn + tn + 64];
#pragma unroll
    for (int i = 0; i < 8; i++) {
        int row = bm + tm + ((i < 4) ? i : (i + 60));  // tm+{0..3}, tm+64+{0..3}
        float4 o0, o1;
        unpack2(acc[i][0], o0.x, o0.y);
        unpack2(acc[i][1], o0.z, o0.w);
        unpack2(acc[i][2], o1.x, o1.y);
        unpack2(acc[i][3], o1.z, o1.w);
        o0.x += bb0.x; o0.y += bb0.y; o0.z += bb0.z; o0.w += bb0.w;
        o1.x += bb1.x; o1.y += bb1.y; o1.z += bb1.z; o1.w += bb1.w;
        *(float4*)&g_proj[(size_t)row * ODIM + bn + tn] = o0;
        *(float4*)&g_proj[(size_t)row * ODIM + bn + tn + 64] = o1;
    }
}

// ---------------- score[m] = dot(x[m,:], score_w) + score_b ----------------
__global__ __launch_bounds__(256) void score_kernel(const float* __restrict__ x,
                                                    const float* __restrict__ sw,
                                                    const float* __restrict__ sb) {
    int row = blockIdx.x * 8 + (threadIdx.x >> 5);
    int lane = threadIdx.x & 31;
    const float4* xr = (const float4*)(x + (size_t)row * KDIM);
    const float4* w4 = (const float4*)sw;
    float acc = 0.f;
#pragma unroll
    for (int i = 0; i < 4; i++) {
        float4 a = xr[lane + 32 * i];
        float4 b = w4[lane + 32 * i];
        acc += a.x * b.x + a.y * b.y + a.z * b.z + a.w * b.w;
    }
#pragma unroll
    for (int off = 16; off; off >>= 1) acc += __shfl_xor_sync(0xffffffffu, acc, off);
    if (lane == 0) g_score[row] = acc + sb[0];
}

// ---------------- window attention: LN + softmax over 25 scores, weighted sum ----------------
// grid (28, 8): block = (hh, n). 256 threads.
__global__ __launch_bounds__(256) void window_kernel(const float* __restrict__ ln_w,
                                                     const float* __restrict__ ln_b,
                                                     float* __restrict__ out) {
    const int hh = blockIdx.x;  // 0..27
    const int n = blockIdx.y;   // 0..7
    __shared__ float s_sc[160];          // scores rows hh..hh+4, w 0..31
    __shared__ float s_w[28][25];        // softmax weights per window
    __shared__ __align__(16) float ps[5][32][68];  // proj tile, 64 channels, pad 68

    const int tid = threadIdx.x;
    if (tid < 160)
        s_sc[tid] = g_score[(size_t)(n * 32 + hh + (tid >> 5)) * 32 + (tid & 31)];
    __syncthreads();

    if (tid < 28) {
        const int ww = tid;
        float v[25];
        float mu = 0.f;
#pragma unroll
        for (int ki = 0; ki < 5; ki++)
#pragma unroll
            for (int kj = 0; kj < 5; kj++) {
                float t = s_sc[ki * 32 + ww + kj];
                v[ki * 5 + kj] = t;
                mu += t;
            }
        mu *= (1.f / 25.f);
        float var = 0.f;
#pragma unroll
        for (int k = 0; k < 25; k++) {
            float d = v[k] - mu;
            var += d * d;
        }
        var *= (1.f / 25.f);
        float inv = rsqrtf(var + 1e-5f);
        float mx = -1e30f;
#pragma unroll
        for (int k = 0; k < 25; k++) {
            v[k] = (v[k] - mu) * inv * ln_w[k] + ln_b[k];
            mx = fmaxf(mx, v[k]);
        }
        float s = 0.f;
#pragma unroll
        for (int k = 0; k < 25; k++) {
            v[k] = __expf(v[k] - mx);
            s += v[k];
        }
        float r = 1.f / s;
#pragma unroll
        for (int k = 0; k < 25; k++) s_w[ww][k] = v[k] * r;
    }
    __syncthreads();

    const int ww = tid & 31;
    const int cq = tid >> 5;  // 0..7 (channel quad within chunk)
    const bool act = (ww < HH);
    float wt[25];
    const int wsrc = act ? ww : 0;
#pragma unroll
    for (int k = 0; k < 25; k++) wt[k] = s_w[wsrc][k];

    for (int c0 = 0; c0 < ODIM; c0 += 64) {
        __syncthreads();
        // stage proj[hh..hh+4][0..31][c0..c0+63] into smem (coalesced float4)
        for (int i = tid; i < 2560; i += 256) {
            int pos = i >> 4;  // 0..159
            int q = i & 15;
            int ki = pos >> 5, w = pos & 31;
            *(float4*)&ps[ki][w][q << 2] =
                *(const float4*)&g_proj[(size_t)((n * 32 + hh + ki) * 32 + w) * ODIM + c0 + (q << 2)];
        }
        __syncthreads();
        if (act) {
#pragma unroll
            for (int rep = 0; rep < 2; rep++) {
                int cq4 = cq + rep * 8;  // 0..15
                float4 acc = {0.f, 0.f, 0.f, 0.f};
#pragma unroll
                for (int ki = 0; ki < 5; ki++)
#pragma unroll
                    for (int kj = 0; kj < 5; kj++) {
                        float wv = wt[ki * 5 + kj];
                        float4 p = *(const float4*)&ps[ki][ww + kj][cq4 << 2];
                        acc.x = fmaf(wv, p.x, acc.x);
                        acc.y = fmaf(wv, p.y, acc.y);
                        acc.z = fmaf(wv, p.z, acc.z);
                        acc.w = fmaf(wv, p.w, acc.w);
                    }
                int c = c0 + (cq4 << 2);
                size_t ob = ((size_t)(n * 512 + c) * HH + hh) * HH + ww;
                out[ob] = acc.x;
                out[ob + 784] = acc.y;
                out[ob + 1568] = acc.z;
                out[ob + 2352] = acc.w;
            }
        }
    }
}

extern "C" void kernel_launch(void* const* d_in, const int* in_sizes, int n_in,
                              void* d_out, int out_size) {
    const float* x       = (const float*)d_in[0];
    const float* proj_w  = (const float*)d_in[1];
    const float* proj_b  = (const float*)d_in[2];
    const float* score_w = (const float*)d_in[3];
    const float* score_b = (const float*)d_in[4];
    const float* ln_w    = (const float*)d_in[5];
    const float* ln_b    = (const float*)d_in[6];
    float* out = (float*)d_out;

    gemm_kernel<<<dim3(4, 64), 256>>>(x, proj_w, proj_b);
    score_kernel<<<1024, 256>>>(x, score_w, score_b);
    window_kernel<<<dim3(HH, 8), 256>>>(ln_w, ln_b, out);
}

// round 3
// speedup vs baseline: 1.6050x; 1.6050x over previous
#include <cuda_runtime.h>
#include <cuda_bf16.h>
#include <cstdint>

// x: (8,512,32,32) fp32 == xr[8192][512]; proj_w (512,512); proj_b (512)
// score_w (512); score_b (1); ln_w (25); ln_b (25); out (8,512,28,28) fp32

#define M_ROWS 8192
#define KDIM   512
#define ODIM   512
#define HH     28

// ---------------- scratch ----------------
__device__ float g_proj[M_ROWS * ODIM];                 // 16 MB
__device__ float g_score[M_ROWS];
__device__ __nv_bfloat16 g_A_hi[M_ROWS * KDIM];
__device__ __nv_bfloat16 g_A_lo[M_ROWS * KDIM];
__device__ __nv_bfloat16 g_W_hi[ODIM * KDIM];
__device__ __nv_bfloat16 g_W_lo[ODIM * KDIM];

// ---------------- helpers ----------------
__device__ __forceinline__ uint32_t smem_u32(const void* p) {
    uint32_t a;
    asm("{ .reg .u64 t; cvta.to.shared.u64 t, %1; cvt.u32.u64 %0, t; }" : "=r"(a) : "l"(p));
    return a;
}
__device__ __forceinline__ void cp_async16(uint32_t sa, const void* ga) {
    asm volatile("cp.async.cg.shared.global [%0], [%1], 16;" :: "r"(sa), "l"(ga) : "memory");
}
__device__ __forceinline__ void cp_commit() {
    asm volatile("cp.async.commit_group;" ::: "memory");
}
__device__ __forceinline__ void cp_wait1() {
    asm volatile("cp.async.wait_group 1;" ::: "memory");
}
__device__ __forceinline__ void cp_wait0() {
    asm volatile("cp.async.wait_group 0;" ::: "memory");
}
__device__ __forceinline__ void ldsm4(uint32_t* r, uint32_t a) {
    asm volatile("ldmatrix.sync.aligned.m8n8.x4.shared.b16 {%0,%1,%2,%3}, [%4];"
                 : "=r"(r[0]), "=r"(r[1]), "=r"(r[2]), "=r"(r[3]) : "r"(a));
}
__device__ __forceinline__ void mma_bf16(float* c, const uint32_t* a, const uint32_t* b) {
    asm volatile(
        "mma.sync.aligned.m16n8k16.row.col.f32.bf16.bf16.f32 "
        "{%0,%1,%2,%3}, {%4,%5,%6,%7}, {%8,%9}, {%0,%1,%2,%3};"
        : "+f"(c[0]), "+f"(c[1]), "+f"(c[2]), "+f"(c[3])
        : "r"(a[0]), "r"(a[1]), "r"(a[2]), "r"(a[3]), "r"(b[0]), "r"(b[1]));
}

// ---------------- convert + score ----------------
// rows 0..8191: x -> A_hi/A_lo + score dot; rows 8192..8703: proj_w -> W_hi/W_lo
__global__ __launch_bounds__(256) void convert_kernel(const float* __restrict__ x,
                                                      const float* __restrict__ pw,
                                                      const float* __restrict__ sw,
                                                      const float* __restrict__ sb) {
    const int row = blockIdx.x * 8 + (threadIdx.x >> 5);
    const int lane = threadIdx.x & 31;
    const bool isX = row < M_ROWS;
    const float4* src = (const float4*)(isX ? x + (size_t)row * KDIM
                                            : pw + (size_t)(row - M_ROWS) * KDIM);
    __nv_bfloat16* dh = isX ? g_A_hi + (size_t)row * KDIM : g_W_hi + (size_t)(row - M_ROWS) * KDIM;
    __nv_bfloat16* dl = isX ? g_A_lo + (size_t)row * KDIM : g_W_lo + (size_t)(row - M_ROWS) * KDIM;
    const float4* w4 = (const float4*)sw;
    float acc = 0.f;
#pragma unroll
    for (int j = 0; j < 4; j++) {
        int idx = lane + 32 * j;
        float4 v = src[idx];
        __nv_bfloat16 h0 = __float2bfloat16(v.x), h1 = __float2bfloat16(v.y);
        __nv_bfloat16 h2 = __float2bfloat16(v.z), h3 = __float2bfloat16(v.w);
        __nv_bfloat16 l0 = __float2bfloat16(v.x - __bfloat162float(h0));
        __nv_bfloat16 l1 = __float2bfloat16(v.y - __bfloat162float(h1));
        __nv_bfloat16 l2 = __float2bfloat16(v.z - __bfloat162float(h2));
        __nv_bfloat16 l3 = __float2bfloat16(v.w - __bfloat162float(h3));
        ((__nv_bfloat162*)dh)[idx * 2]     = __nv_bfloat162(h0, h1);
        ((__nv_bfloat162*)dh)[idx * 2 + 1] = __nv_bfloat162(h2, h3);
        ((__nv_bfloat162*)dl)[idx * 2]     = __nv_bfloat162(l0, l1);
        ((__nv_bfloat162*)dl)[idx * 2 + 1] = __nv_bfloat162(l2, l3);
        if (isX) {
            float4 w = w4[idx];
            acc += v.x * w.x + v.y * w.y + v.z * w.z + v.w * w.w;
        }
    }
    if (isX) {
#pragma unroll
        for (int off = 16; off; off >>= 1) acc += __shfl_xor_sync(0xffffffffu, acc, off);
        if (lane == 0) g_score[row] = acc + sb[0];
    }
}

// ---------------- HMMA GEMM ----------------
// CTA 128x128, 8 warps (4 M x 2 N), warp tile 32x64, k-chunk 16, cp.async double-buffer.
// SMEM per stage: 4 regions (A_hi, A_lo, W_hi, W_lo), each 128 rows x 24 bf16 (48B, 16 used).
#define ROWB     48
#define REGION   (128 * ROWB)          // 6144
#define STAGEB   (4 * REGION)          // 24576
#define NCHUNK   32

__global__ __launch_bounds__(256, 2) void gemm_mma(const float* __restrict__ bias) {
    __shared__ __align__(16) char smem[2 * STAGEB];   // 49152 = 48KB
    const int tid = threadIdx.x;
    const int lane = tid & 31;
    const int wid = tid >> 5;
    const int warpM = wid >> 1;   // 0..3
    const int warpN = wid & 1;    // 0..1
    const int bm = blockIdx.y * 128;
    const int bn = blockIdx.x * 128;
    const uint32_t sbase = smem_u32(smem);

    // loader: each thread handles row = tid>>1, q = tid&1 for all 4 regions
    const int lrow = tid >> 1;
    const int lq = tid & 1;
    const __nv_bfloat16* gsrc[4];
    gsrc[0] = g_A_hi + (size_t)(bm + lrow) * KDIM + lq * 8;
    gsrc[1] = g_A_lo + (size_t)(bm + lrow) * KDIM + lq * 8;
    gsrc[2] = g_W_hi + (size_t)(bn + lrow) * KDIM + lq * 8;
    gsrc[3] = g_W_lo + (size_t)(bn + lrow) * KDIM + lq * 8;
    const uint32_t sdst = sbase + lrow * ROWB + lq * 16;

    // ldmatrix lane offsets
    const int t = lane >> 3;
    const uint32_t a_off = (uint32_t)((warpM * 32 + (t & 1) * 8 + (lane & 7)) * ROWB + (t >> 1) * 16);
    const uint32_t b_off = (uint32_t)((warpN * 64 + (t >> 1) * 8 + (lane & 7)) * ROWB + (t & 1) * 16);

    float acc[2][8][4];
#pragma unroll
    for (int i = 0; i < 2; i++)
#pragma unroll
        for (int j = 0; j < 8; j++)
#pragma unroll
            for (int q = 0; q < 4; q++) acc[i][j][q] = 0.f;

    // prologue: stage 0
#pragma unroll
    for (int r = 0; r < 4; r++) cp_async16(sdst + r * REGION, gsrc[r]);
    cp_commit();

    for (int it = 0; it < NCHUNK; it++) {
        const int st = it & 1;
        if (it + 1 < NCHUNK) {
#pragma unroll
            for (int r = 0; r < 4; r++)
                cp_async16(sdst + (st ^ 1) * STAGEB + r * REGION, gsrc[r] + (it + 1) * 16);
            cp_commit();
            cp_wait1();
        } else {
            cp_wait0();
        }
        __syncthreads();

        const uint32_t stb = sbase + st * STAGEB;
        uint32_t ah[2][4], al[2][4];
        ldsm4(ah[0], stb + a_off);
        ldsm4(ah[1], stb + a_off + 16 * ROWB);
        ldsm4(al[0], stb + REGION + a_off);
        ldsm4(al[1], stb + REGION + a_off + 16 * ROWB);
#pragma unroll
        for (int h = 0; h < 2; h++) {
            uint32_t bh[2][4], bl[2][4];
            ldsm4(bh[0], stb + 2 * REGION + b_off + (h * 32) * ROWB);
            ldsm4(bh[1], stb + 2 * REGION + b_off + (h * 32 + 16) * ROWB);
            ldsm4(bl[0], stb + 3 * REGION + b_off + (h * 32) * ROWB);
            ldsm4(bl[1], stb + 3 * REGION + b_off + (h * 32 + 16) * ROWB);
#pragma unroll
            for (int mt = 0; mt < 2; mt++)
#pragma unroll
                for (int ntl = 0; ntl < 4; ntl++) {
                    float* c = acc[mt][h * 4 + ntl];
                    const uint32_t* ph = &bh[ntl >> 1][(ntl & 1) * 2];
                    const uint32_t* pl = &bl[ntl >> 1][(ntl & 1) * 2];
                    mma_bf16(c, ah[mt], ph);
                    mma_bf16(c, ah[mt], pl);
                    mma_bf16(c, al[mt], ph);
                }
        }
        __syncthreads();
    }

    // epilogue: acc -> g_proj (+bias)
#pragma unroll
    for (int nt = 0; nt < 8; nt++) {
        const int c = bn + warpN * 64 + nt * 8 + (lane & 3) * 2;
        float2 bb = *(const float2*)&bias[c];
#pragma unroll
        for (int mt = 0; mt < 2; mt++) {
            const int r = bm + warpM * 32 + mt * 16 + (lane >> 2);
            float2 o0 = {acc[mt][nt][0] + bb.x, acc[mt][nt][1] + bb.y};
            float2 o1 = {acc[mt][nt][2] + bb.x, acc[mt][nt][3] + bb.y};
            *(float2*)&g_proj[(size_t)r * ODIM + c] = o0;
            *(float2*)&g_proj[(size_t)(r + 8) * ODIM + c] = o1;
        }
    }
}

// ---------------- window attention ----------------
__global__ __launch_bounds__(256) void window_kernel(const float* __restrict__ ln_w,
                                                     const float* __restrict__ ln_b,
                                                     float* __restrict__ out) {
    const int hh = blockIdx.x;
    const int n = blockIdx.y;
    __shared__ float s_sc[160];
    __shared__ float s_w[28][25];
    __shared__ __align__(16) float ps[5][32][68];

    const int tid = threadIdx.x;
    if (tid < 160)
        s_sc[tid] = g_score[(size_t)(n * 32 + hh + (tid >> 5)) * 32 + (tid & 31)];
    __syncthreads();

    if (tid < 28) {
        const int ww = tid;
        float v[25];
        float mu = 0.f;
#pragma unroll
        for (int ki = 0; ki < 5; ki++)
#pragma unroll
            for (int kj = 0; kj < 5; kj++) {
                float tv = s_sc[ki * 32 + ww + kj];
                v[ki * 5 + kj] = tv;
                mu += tv;
            }
        mu *= (1.f / 25.f);
        float var = 0.f;
#pragma unroll
        for (int k = 0; k < 25; k++) {
            float d = v[k] - mu;
            var += d * d;
        }
        var *= (1.f / 25.f);
        float inv = rsqrtf(var + 1e-5f);
        float mx = -1e30f;
#pragma unroll
        for (int k = 0; k < 25; k++) {
            v[k] = (v[k] - mu) * inv * ln_w[k] + ln_b[k];
            mx = fmaxf(mx, v[k]);
        }
        float s = 0.f;
#pragma unroll
        for (int k = 0; k < 25; k++) {
            v[k] = __expf(v[k] - mx);
            s += v[k];
        }
        float r = 1.f / s;
#pragma unroll
        for (int k = 0; k < 25; k++) s_w[ww][k] = v[k] * r;
    }
    __syncthreads();

    const int ww = tid & 31;
    const int cq = tid >> 5;
    const bool act = (ww < HH);
    float wt[25];
    const int wsrc = act ? ww : 0;
#pragma unroll
    for (int k = 0; k < 25; k++) wt[k] = s_w[wsrc][k];

    for (int c0 = 0; c0 < ODIM; c0 += 64) {
        __syncthreads();
        for (int i = tid; i < 2560; i += 256) {
            int pos = i >> 4;
            int q = i & 15;
            int ki = pos >> 5, w = pos & 31;
            *(float4*)&ps[ki][w][q << 2] =
                *(const float4*)&g_proj[(size_t)((n * 32 + hh + ki) * 32 + w) * ODIM + c0 + (q << 2)];
        }
        __syncthreads();
        if (act) {
#pragma unroll
            for (int rep = 0; rep < 2; rep++) {
                int cq4 = cq + rep * 8;
                float4 acc = {0.f, 0.f, 0.f, 0.f};
#pragma unroll
                for (int ki = 0; ki < 5; ki++)
#pragma unroll
                    for (int kj = 0; kj < 5; kj++) {
                        float wv = wt[ki * 5 + kj];
                        float4 p = *(const float4*)&ps[ki][ww + kj][cq4 << 2];
                        acc.x = fmaf(wv, p.x, acc.x);
                        acc.y = fmaf(wv, p.y, acc.y);
                        acc.z = fmaf(wv, p.z, acc.z);
                        acc.w = fmaf(wv, p.w, acc.w);
                    }
                int c = c0 + (cq4 << 2);
                size_t ob = ((size_t)(n * 512 + c) * HH + hh) * HH + ww;
                out[ob] = acc.x;
                out[ob + 784] = acc.y;
                out[ob + 1568] = acc.z;
                out[ob + 2352] = acc.w;
            }
        }
    }
}

extern "C" void kernel_launch(void* const* d_in, const int* in_sizes, int n_in,
                              void* d_out, int out_size) {
    const float* x       = (const float*)d_in[0];
    const float* proj_w  = (const float*)d_in[1];
    const float* proj_b  = (const float*)d_in[2];
    const float* score_w = (const float*)d_in[3];
    const float* score_b = (const float*)d_in[4];
    const float* ln_w    = (const float*)d_in[5];
    const float* ln_b    = (const float*)d_in[6];
    float* out = (float*)d_out;

    convert_kernel<<<1088, 256>>>(x, proj_w, score_w, score_b);
    gemm_mma<<<dim3(4, 64), 256>>>(proj_b);
    window_kernel<<<dim3(HH, 8), 256>>>(ln_w, ln_b, out);
}

// round 4
// speedup vs baseline: 2.1492x; 1.3391x over previous
#include <cuda_runtime.h>
#include <cuda_fp16.h>
#include <cstdint>

// x: (8,512,32,32) fp32 == xr[8192][512]; proj_w (512,512); proj_b (512)
// score_w (512); score_b (1); ln_w (25); ln_b (25); out (8,512,28,28) fp32

#define M_ROWS 8192
#define KDIM   512
#define ODIM   512
#define HH     28

// ---------------- scratch ----------------
__device__ float g_proj[M_ROWS * ODIM];     // 16 MB
__device__ float g_score[M_ROWS];
__device__ __half g_A[M_ROWS * KDIM];       // 8 MB   (fp16(x))
__device__ __half g_Wh[ODIM * KDIM];        // 0.5 MB (fp16(w))
__device__ __half g_Wl[ODIM * KDIM];        // 0.5 MB (fp16(w - wh))

// ---------------- helpers ----------------
__device__ __forceinline__ uint32_t smem_u32(const void* p) {
    uint32_t a;
    asm("{ .reg .u64 t; cvta.to.shared.u64 t, %1; cvt.u32.u64 %0, t; }" : "=r"(a) : "l"(p));
    return a;
}
__device__ __forceinline__ void cp_async16(uint32_t sa, const void* ga) {
    asm volatile("cp.async.cg.shared.global [%0], [%1], 16;" :: "r"(sa), "l"(ga) : "memory");
}
__device__ __forceinline__ void cp_commit() {
    asm volatile("cp.async.commit_group;" ::: "memory");
}
__device__ __forceinline__ void cp_wait2() {
    asm volatile("cp.async.wait_group 2;" ::: "memory");
}
__device__ __forceinline__ void ldsm4(uint32_t* r, uint32_t a) {
    asm volatile("ldmatrix.sync.aligned.m8n8.x4.shared.b16 {%0,%1,%2,%3}, [%4];"
                 : "=r"(r[0]), "=r"(r[1]), "=r"(r[2]), "=r"(r[3]) : "r"(a));
}
__device__ __forceinline__ void mma_f16(float* c, const uint32_t* a, const uint32_t* b) {
    asm volatile(
        "mma.sync.aligned.m16n8k16.row.col.f32.f16.f16.f32 "
        "{%0,%1,%2,%3}, {%4,%5,%6,%7}, {%8,%9}, {%0,%1,%2,%3};"
        : "+f"(c[0]), "+f"(c[1]), "+f"(c[2]), "+f"(c[3])
        : "r"(a[0]), "r"(a[1]), "r"(a[2]), "r"(a[3]), "r"(b[0]), "r"(b[1]));
}

// ---------------- convert + score ----------------
// rows 0..8191: x -> g_A fp16 + score dot.  rows 8192..8703: proj_w -> Wh/Wl fp16.
__global__ __launch_bounds__(256) void convert_kernel(const float* __restrict__ x,
                                                      const float* __restrict__ pw,
                                                      const float* __restrict__ sw,
                                                      const float* __restrict__ sb) {
    const int row = blockIdx.x * 8 + (threadIdx.x >> 5);
    const int lane = threadIdx.x & 31;
    const bool isX = row < M_ROWS;
    const float4* src = (const float4*)(isX ? x + (size_t)row * KDIM
                                            : pw + (size_t)(row - M_ROWS) * KDIM);
    const float4* w4 = (const float4*)sw;
    float acc = 0.f;
#pragma unroll
    for (int p = 0; p < 2; p++) {
        const int j = lane + 32 * p;            // float4-pair index, 0..63
        float4 v0 = src[2 * j];
        float4 v1 = src[2 * j + 1];
        __half2 h0 = __floats2half2_rn(v0.x, v0.y);
        __half2 h1 = __floats2half2_rn(v0.z, v0.w);
        __half2 h2 = __floats2half2_rn(v1.x, v1.y);
        __half2 h3 = __floats2half2_rn(v1.z, v1.w);
        uint4 uh;
        uh.x = *(uint32_t*)&h0; uh.y = *(uint32_t*)&h1;
        uh.z = *(uint32_t*)&h2; uh.w = *(uint32_t*)&h3;
        if (isX) {
            ((uint4*)(g_A + (size_t)row * KDIM))[j] = uh;
            float4 w0 = w4[2 * j], w1 = w4[2 * j + 1];
            acc += v0.x * w0.x + v0.y * w0.y + v0.z * w0.z + v0.w * w0.w;
            acc += v1.x * w1.x + v1.y * w1.y + v1.z * w1.z + v1.w * w1.w;
        } else {
            const int wr = row - M_ROWS;
            ((uint4*)(g_Wh + (size_t)wr * KDIM))[j] = uh;
            float2 f0 = __half22float2(h0), f1 = __half22float2(h1);
            float2 f2 = __half22float2(h2), f3 = __half22float2(h3);
            __half2 l0 = __floats2half2_rn(v0.x - f0.x, v0.y - f0.y);
            __half2 l1 = __floats2half2_rn(v0.z - f1.x, v0.w - f1.y);
            __half2 l2 = __floats2half2_rn(v1.x - f2.x, v1.y - f2.y);
            __half2 l3 = __floats2half2_rn(v1.z - f3.x, v1.w - f3.y);
            uint4 ul;
            ul.x = *(uint32_t*)&l0; ul.y = *(uint32_t*)&l1;
            ul.z = *(uint32_t*)&l2; ul.w = *(uint32_t*)&l3;
            ((uint4*)(g_Wl + (size_t)wr * KDIM))[j] = ul;
        }
    }
    if (isX) {
#pragma unroll
        for (int off = 16; off; off >>= 1) acc += __shfl_xor_sync(0xffffffffu, acc, off);
        if (lane == 0) g_score[row] = acc + sb[0];
    }
}

// ---------------- HMMA GEMM (2-term fp16 split) ----------------
// CTA 128x128, 8 warps (4M x 2N), warp tile 32x64, k-chunk 16, 4-stage cp.async.
// Stage: 3 regions (A, Wh, Wl), each 128 rows x 32B (16 fp16), XOR-swizzled.
#define ROWB    32
#define REGION  (128 * ROWB)            // 4096
#define STAGEB  (3 * REGION)            // 12288
#define NSTAGE  4
#define NCHUNK  32

__device__ __forceinline__ uint32_t swz(int row, int q) {
    return (uint32_t)(row * ROWB + ((q ^ ((row >> 2) & 1)) << 4));
}

__global__ __launch_bounds__(256, 2) void gemm_mma(const float* __restrict__ bias) {
    __shared__ __align__(16) char smem[NSTAGE * STAGEB];   // 49152 = 48KB
    const int tid = threadIdx.x;
    const int lane = tid & 31;
    const int wid = tid >> 5;
    const int warpM = wid >> 1;   // 0..3
    const int warpN = wid & 1;    // 0..1
    const int bm = blockIdx.y * 128;
    const int bn = blockIdx.x * 128;
    const uint32_t sbase = smem_u32(smem);

    // loader: thread -> (row = tid>>1, q = tid&1), 3 regions
    const int lrow = tid >> 1;
    const int lq = tid & 1;
    const __half* gA = g_A + (size_t)(bm + lrow) * KDIM + lq * 8;
    const __half* gH = g_Wh + (size_t)(bn + lrow) * KDIM + lq * 8;
    const __half* gL = g_Wl + (size_t)(bn + lrow) * KDIM + lq * 8;
    const uint32_t soff = swz(lrow, lq);

    // ldmatrix lane offsets
    const int t = lane >> 3;
    const uint32_t a_sw0 = swz(warpM * 32 + (t & 1) * 8 + (lane & 7), t >> 1);
    const uint32_t a_sw1 = swz(warpM * 32 + 16 + (t & 1) * 8 + (lane & 7), t >> 1);
    const int brow = warpN * 64 + (t >> 1) * 8 + (lane & 7);
    const int bq = t & 1;

    float acc[2][8][4];
#pragma unroll
    for (int i = 0; i < 2; i++)
#pragma unroll
        for (int j = 0; j < 8; j++)
#pragma unroll
            for (int q = 0; q < 4; q++) acc[i][j][q] = 0.f;

    // prologue: stages 0..2
#pragma unroll
    for (int s = 0; s < 3; s++) {
        const uint32_t st = sbase + s * STAGEB;
        cp_async16(st + soff, gA + s * 16);
        cp_async16(st + REGION + soff, gH + s * 16);
        cp_async16(st + 2 * REGION + soff, gL + s * 16);
        cp_commit();
    }

    for (int it = 0; it < NCHUNK; it++) {
        cp_wait2();
        __syncthreads();
        if (it + 3 < NCHUNK) {
            const uint32_t st = sbase + ((it + 3) & 3) * STAGEB;
            cp_async16(st + soff, gA + (it + 3) * 16);
            cp_async16(st + REGION + soff, gH + (it + 3) * 16);
            cp_async16(st + 2 * REGION + soff, gL + (it + 3) * 16);
        }
        cp_commit();

        const uint32_t stb = sbase + (it & 3) * STAGEB;
        uint32_t ah[2][4];
        ldsm4(ah[0], stb + a_sw0);
        ldsm4(ah[1], stb + a_sw1);
#pragma unroll
        for (int h = 0; h < 2; h++) {
            uint32_t bh[2][4], bl[2][4];
            ldsm4(bh[0], stb + REGION + swz(brow + h * 32, bq));
            ldsm4(bh[1], stb + REGION + swz(brow + h * 32 + 16, bq));
            ldsm4(bl[0], stb + 2 * REGION + swz(brow + h * 32, bq));
            ldsm4(bl[1], stb + 2 * REGION + swz(brow + h * 32 + 16, bq));
#pragma unroll
            for (int mt = 0; mt < 2; mt++)
#pragma unroll
                for (int ntl = 0; ntl < 4; ntl++) {
                    float* c = acc[mt][h * 4 + ntl];
                    mma_f16(c, ah[mt], &bh[ntl >> 1][(ntl & 1) * 2]);
                    mma_f16(c, ah[mt], &bl[ntl >> 1][(ntl & 1) * 2]);
                }
        }
    }

    // epilogue: acc -> g_proj (+bias)
#pragma unroll
    for (int nt = 0; nt < 8; nt++) {
        const int c = bn + warpN * 64 + nt * 8 + (lane & 3) * 2;
        float2 bb = *(const float2*)&bias[c];
#pragma unroll
        for (int mt = 0; mt < 2; mt++) {
            const int r = bm + warpM * 32 + mt * 16 + (lane >> 2);
            float2 o0 = {acc[mt][nt][0] + bb.x, acc[mt][nt][1] + bb.y};
            float2 o1 = {acc[mt][nt][2] + bb.x, acc[mt][nt][3] + bb.y};
            *(float2*)&g_proj[(size_t)r * ODIM + c] = o0;
            *(float2*)&g_proj[(size_t)(r + 8) * ODIM + c] = o1;
        }
    }
}

// ---------------- window attention ----------------
__global__ __launch_bounds__(256) void window_kernel(const float* __restrict__ ln_w,
                                                     const float* __restrict__ ln_b,
                                                     float* __restrict__ out) {
    const int hh = blockIdx.x;
    const int n = blockIdx.y;
    __shared__ float s_sc[160];
    __shared__ float s_w[28][25];
    __shared__ __align__(16) float ps[5][32][68];

    const int tid = threadIdx.x;
    if (tid < 160)
        s_sc[tid] = g_score[(size_t)(n * 32 + hh + (tid >> 5)) * 32 + (tid & 31)];
    __syncthreads();

    if (tid < 28) {
        const int ww = tid;
        float v[25];
        float mu = 0.f;
#pragma unroll
        for (int ki = 0; ki < 5; ki++)
#pragma unroll
            for (int kj = 0; kj < 5; kj++) {
                float tv = s_sc[ki * 32 + ww + kj];
                v[ki * 5 + kj] = tv;
                mu += tv;
            }
        mu *= (1.f / 25.f);
        float var = 0.f;
#pragma unroll
        for (int k = 0; k < 25; k++) {
            float d = v[k] - mu;
            var += d * d;
        }
        var *= (1.f / 25.f);
        float inv = rsqrtf(var + 1e-5f);
        float mx = -1e30f;
#pragma unroll
        for (int k = 0; k < 25; k++) {
            v[k] = (v[k] - mu) * inv * ln_w[k] + ln_b[k];
            mx = fmaxf(mx, v[k]);
        }
        float s = 0.f;
#pragma unroll
        for (int k = 0; k < 25; k++) {
            v[k] = __expf(v[k] - mx);
            s += v[k];
        }
        float r = 1.f / s;
#pragma unroll
        for (int k = 0; k < 25; k++) s_w[ww][k] = v[k] * r;
    }
    __syncthreads();

    const int ww = tid & 31;
    const int cq = tid >> 5;
    const bool act = (ww < HH);
    float wt[25];
    const int wsrc = act ? ww : 0;
#pragma unroll
    for (int k = 0; k < 25; k++) wt[k] = s_w[wsrc][k];

    for (int c0 = 0; c0 < ODIM; c0 += 64) {
        __syncthreads();
        for (int i = tid; i < 2560; i += 256) {
            int pos = i >> 4;
            int q = i & 15;
            int ki = pos >> 5, w = pos & 31;
            *(float4*)&ps[ki][w][q << 2] =
                *(const float4*)&g_proj[(size_t)((n * 32 + hh + ki) * 32 + w) * ODIM + c0 + (q << 2)];
        }
        __syncthreads();
        if (act) {
#pragma unroll
            for (int rep = 0; rep < 2; rep++) {
                int cq4 = cq + rep * 8;
                float4 acc = {0.f, 0.f, 0.f, 0.f};
#pragma unroll
                for (int ki = 0; ki < 5; ki++)
#pragma unroll
                    for (int kj = 0; kj < 5; kj++) {
                        float wv = wt[ki * 5 + kj];
                        float4 p = *(const float4*)&ps[ki][ww + kj][cq4 << 2];
                        acc.x = fmaf(wv, p.x, acc.x);
                        acc.y = fmaf(wv, p.y, acc.y);
                        acc.z = fmaf(wv, p.z, acc.z);
                        acc.w = fmaf(wv, p.w, acc.w);
                    }
                int c = c0 + (cq4 << 2);
                size_t ob = ((size_t)(n * 512 + c) * HH + hh) * HH + ww;
                out[ob] = acc.x;
                out[ob + 784] = acc.y;
                out[ob + 1568] = acc.z;
                out[ob + 2352] = acc.w;
            }
        }
    }
}

extern "C" void kernel_launch(void* const* d_in, const int* in_sizes, int n_in,
                              void* d_out, int out_size) {
    const float* x       = (const float*)d_in[0];
    const float* proj_w  = (const float*)d_in[1];
    const float* proj_b  = (const float*)d_in[2];
    const float* score_w = (const float*)d_in[3];
    const float* score_b = (const float*)d_in[4];
    const float* ln_w    = (const float*)d_in[5];
    const float* ln_b    = (const float*)d_in[6];
    float* out = (float*)d_out;

    convert_kernel<<<1088, 256>>>(x, proj_w, score_w, score_b);
    gemm_mma<<<dim3(4, 64), 256>>>(proj_b);
    window_kernel<<<dim3(HH, 8), 256>>>(ln_w, ln_b, out);
}

// round 5
// speedup vs baseline: 2.1984x; 1.0229x over previous
#include <cuda_runtime.h>
#include <cuda_fp16.h>
#include <cstdint>

// x: (8,512,32,32) fp32 == xr[8192][512]; proj_w (512,512); proj_b (512)
// score_w (512); score_b (1); ln_w (25); ln_b (25); out (8,512,28,28) fp32

#define M_ROWS 8192
#define KDIM   512
#define ODIM   512
#define HH     28

// ---------------- scratch ----------------
__device__ float g_proj[M_ROWS * ODIM];     // 16 MB
__device__ float g_score[M_ROWS];
__device__ __half g_A[M_ROWS * KDIM];       // 8 MB   (fp16(x))
__device__ __half g_Wh[ODIM * KDIM];        // 0.5 MB (fp16(w))
__device__ __half g_Wl[ODIM * KDIM];        // 0.5 MB (fp16(w - wh))

// ---------------- helpers ----------------
__device__ __forceinline__ uint32_t smem_u32(const void* p) {
    uint32_t a;
    asm("{ .reg .u64 t; cvta.to.shared.u64 t, %1; cvt.u32.u64 %0, t; }" : "=r"(a) : "l"(p));
    return a;
}
__device__ __forceinline__ void cp_async16(uint32_t sa, const void* ga) {
    asm volatile("cp.async.cg.shared.global [%0], [%1], 16;" :: "r"(sa), "l"(ga) : "memory");
}
__device__ __forceinline__ void cp_commit() {
    asm volatile("cp.async.commit_group;" ::: "memory");
}
__device__ __forceinline__ void cp_wait1() {
    asm volatile("cp.async.wait_group 1;" ::: "memory");
}
__device__ __forceinline__ void ldsm4(uint32_t* r, uint32_t a) {
    asm volatile("ldmatrix.sync.aligned.m8n8.x4.shared.b16 {%0,%1,%2,%3}, [%4];"
                 : "=r"(r[0]), "=r"(r[1]), "=r"(r[2]), "=r"(r[3]) : "r"(a));
}
__device__ __forceinline__ void mma_f16(float* c, const uint32_t* a, const uint32_t* b) {
    asm volatile(
        "mma.sync.aligned.m16n8k16.row.col.f32.f16.f16.f32 "
        "{%0,%1,%2,%3}, {%4,%5,%6,%7}, {%8,%9}, {%0,%1,%2,%3};"
        : "+f"(c[0]), "+f"(c[1]), "+f"(c[2]), "+f"(c[3])
        : "r"(a[0]), "r"(a[1]), "r"(a[2]), "r"(a[3]), "r"(b[0]), "r"(b[1]));
}

// ---------------- convert + score (single pass, MLP 4) ----------------
__global__ __launch_bounds__(256) void convert_kernel(const float* __restrict__ x,
                                                      const float* __restrict__ pw,
                                                      const float* __restrict__ sw,
                                                      const float* __restrict__ sb) {
    const int row = blockIdx.x * 8 + (threadIdx.x >> 5);
    const int lane = threadIdx.x & 31;
    const bool isX = row < M_ROWS;
    const float4* src = (const float4*)(isX ? x + (size_t)row * KDIM
                                            : pw + (size_t)(row - M_ROWS) * KDIM);
    // four independent loads up front
    float4 v0 = src[2 * lane];
    float4 v1 = src[2 * lane + 1];
    float4 v2 = src[2 * lane + 64];
    float4 v3 = src[2 * lane + 65];

    __half2 h0 = __floats2half2_rn(v0.x, v0.y), h1 = __floats2half2_rn(v0.z, v0.w);
    __half2 h2 = __floats2half2_rn(v1.x, v1.y), h3 = __floats2half2_rn(v1.z, v1.w);
    __half2 h4 = __floats2half2_rn(v2.x, v2.y), h5 = __floats2half2_rn(v2.z, v2.w);
    __half2 h6 = __floats2half2_rn(v3.x, v3.y), h7 = __floats2half2_rn(v3.z, v3.w);
    uint4 ua, ub;
    ua.x = *(uint32_t*)&h0; ua.y = *(uint32_t*)&h1; ua.z = *(uint32_t*)&h2; ua.w = *(uint32_t*)&h3;
    ub.x = *(uint32_t*)&h4; ub.y = *(uint32_t*)&h5; ub.z = *(uint32_t*)&h6; ub.w = *(uint32_t*)&h7;

    if (isX) {
        uint4* dst = (uint4*)(g_A + (size_t)row * KDIM);
        dst[lane] = ua;
        dst[lane + 32] = ub;
        const float4* w4 = (const float4*)sw;
        float4 w0 = w4[2 * lane], w1 = w4[2 * lane + 1];
        float4 w2 = w4[2 * lane + 64], w3 = w4[2 * lane + 65];
        float acc = v0.x * w0.x + v0.y * w0.y + v0.z * w0.z + v0.w * w0.w;
        acc += v1.x * w1.x + v1.y * w1.y + v1.z * w1.z + v1.w * w1.w;
        acc += v2.x * w2.x + v2.y * w2.y + v2.z * w2.z + v2.w * w2.w;
        acc += v3.x * w3.x + v3.y * w3.y + v3.z * w3.z + v3.w * w3.w;
#pragma unroll
        for (int off = 16; off; off >>= 1) acc += __shfl_xor_sync(0xffffffffu, acc, off);
        if (lane == 0) g_score[row] = acc + sb[0];
    } else {
        const int wr = row - M_ROWS;
        uint4* dh = (uint4*)(g_Wh + (size_t)wr * KDIM);
        dh[lane] = ua;
        dh[lane + 32] = ub;
        float2 f0 = __half22float2(h0), f1 = __half22float2(h1);
        float2 f2 = __half22float2(h2), f3 = __half22float2(h3);
        float2 f4 = __half22float2(h4), f5 = __half22float2(h5);
        float2 f6 = __half22float2(h6), f7 = __half22float2(h7);
        __half2 l0 = __floats2half2_rn(v0.x - f0.x, v0.y - f0.y);
        __half2 l1 = __floats2half2_rn(v0.z - f1.x, v0.w - f1.y);
        __half2 l2 = __floats2half2_rn(v1.x - f2.x, v1.y - f2.y);
        __half2 l3 = __floats2half2_rn(v1.z - f3.x, v1.w - f3.y);
        __half2 l4 = __floats2half2_rn(v2.x - f4.x, v2.y - f4.y);
        __half2 l5 = __floats2half2_rn(v2.z - f5.x, v2.w - f5.y);
        __half2 l6 = __floats2half2_rn(v3.x - f6.x, v3.y - f6.y);
        __half2 l7 = __floats2half2_rn(v3.z - f7.x, v3.w - f7.y);
        uint4 la, lb;
        la.x = *(uint32_t*)&l0; la.y = *(uint32_t*)&l1; la.z = *(uint32_t*)&l2; la.w = *(uint32_t*)&l3;
        lb.x = *(uint32_t*)&l4; lb.y = *(uint32_t*)&l5; lb.z = *(uint32_t*)&l6; lb.w = *(uint32_t*)&l7;
        uint4* dl = (uint4*)(g_Wl + (size_t)wr * KDIM);
        dl[lane] = la;
        dl[lane + 32] = lb;
    }
}

// ---------------- HMMA GEMM (2-term fp16 split, k-chunk 32, 2-stage) ----------------
// CTA 128x128, 8 warps (4M x 2N). Stage: A(8KB) + Wh(8KB) + Wl(8KB) = 24KB. 2 stages = 48KB.
// Rows are 64B (32 halfs); swizzle: 16B quad q at row r -> q ^ ((r>>1)&3).
#define RGN     8192
#define STAGEB  (3 * RGN)
#define NIT     16

__device__ __forceinline__ uint32_t swz64(int r, int q) {
    return (uint32_t)(r * 64 + ((q ^ ((r >> 1) & 3)) << 4));
}

__global__ __launch_bounds__(256, 2) void gemm_mma(const float* __restrict__ bias) {
    __shared__ __align__(16) char smem[2 * STAGEB];   // 48KB
    const int tid = threadIdx.x;
    const int lane = tid & 31;
    const int wid = tid >> 5;
    const int warpM = wid >> 1;
    const int warpN = wid & 1;
    const int bm = blockIdx.y * 128;
    const int bn = blockIdx.x * 128;
    const uint32_t sbase = smem_u32(smem);

    // loader: 1536 16B-chunks / 256 threads = 6 per thread
    uint32_t ldst[6];
    const __half* lsrc[6];
#pragma unroll
    for (int i = 0; i < 6; i++) {
        int c = tid + 256 * i;
        int region = c >> 9;          // 0:A 1:Wh 2:Wl
        int r = (c & 511) >> 2;
        int q = c & 3;
        ldst[i] = sbase + region * RGN + swz64(r, q);
        const __half* base = (region == 0) ? g_A + (size_t)(bm + r) * KDIM
                           : (region == 1) ? g_Wh + (size_t)(bn + r) * KDIM
                                           : g_Wl + (size_t)(bn + r) * KDIM;
        lsrc[i] = base + q * 8;
    }

    // fragment address components
    const int t = lane >> 3;
    const int arow0 = warpM * 32 + (t & 1) * 8 + (lane & 7);
    const int brow = warpN * 64 + (t >> 1) * 8 + (lane & 7);
    const int aq = t >> 1;
    const int bq = t & 1;

    float acc[2][8][4];
#pragma unroll
    for (int i = 0; i < 2; i++)
#pragma unroll
        for (int j = 0; j < 8; j++)
#pragma unroll
            for (int q = 0; q < 4; q++) acc[i][j][q] = 0.f;

    // prologue: stages 0,1
#pragma unroll
    for (int s = 0; s < 2; s++) {
#pragma unroll
        for (int i = 0; i < 6; i++) cp_async16(ldst[i] + s * STAGEB, lsrc[i] + s * 32);
        cp_commit();
    }

    for (int it = 0; it < NIT; it++) {
        cp_wait1();
        __syncthreads();
        const uint32_t stb = sbase + (it & 1) * STAGEB;

#pragma unroll
        for (int kk = 0; kk < 2; kk++) {
            uint32_t ah[2][4], bb[2][2][4];
            ldsm4(ah[0], stb + swz64(arow0, kk * 2 + aq));
            ldsm4(ah[1], stb + swz64(arow0 + 16, kk * 2 + aq));
            // Wh fragments + MMAs
            ldsm4(bb[0][0], stb + RGN + swz64(brow, kk * 2 + bq));
            ldsm4(bb[0][1], stb + RGN + swz64(brow + 16, kk * 2 + bq));
            ldsm4(bb[1][0], stb + RGN + swz64(brow + 32, kk * 2 + bq));
            ldsm4(bb[1][1], stb + RGN + swz64(brow + 48, kk * 2 + bq));
#pragma unroll
            for (int h = 0; h < 2; h++)
#pragma unroll
                for (int mt = 0; mt < 2; mt++)
#pragma unroll
                    for (int ntl = 0; ntl < 4; ntl++)
                        mma_f16(acc[mt][h * 4 + ntl], ah[mt], &bb[h][ntl >> 1][(ntl & 1) * 2]);
            // Wl fragments + MMAs
            ldsm4(bb[0][0], stb + 2 * RGN + swz64(brow, kk * 2 + bq));
            ldsm4(bb[0][1], stb + 2 * RGN + swz64(brow + 16, kk * 2 + bq));
            ldsm4(bb[1][0], stb + 2 * RGN + swz64(brow + 32, kk * 2 + bq));
            ldsm4(bb[1][1], stb + 2 * RGN + swz64(brow + 48, kk * 2 + bq));
            if (kk == 1) {
                __syncthreads();   // all warps finished reading this stage
                if (it + 2 < NIT) {
#pragma unroll
                    for (int i = 0; i < 6; i++)
                        cp_async16(ldst[i] + (it & 1) * STAGEB, lsrc[i] + (it + 2) * 32);
                }
                cp_commit();
            }
#pragma unroll
            for (int h = 0; h < 2; h++)
#pragma unroll
                for (int mt = 0; mt < 2; mt++)
#pragma unroll
                    for (int ntl = 0; ntl < 4; ntl++)
                        mma_f16(acc[mt][h * 4 + ntl], ah[mt], &bb[h][ntl >> 1][(ntl & 1) * 2]);
        }
    }

    // epilogue
#pragma unroll
    for (int nt = 0; nt < 8; nt++) {
        const int c = bn + warpN * 64 + nt * 8 + (lane & 3) * 2;
        float2 bbias = *(const float2*)&bias[c];
#pragma unroll
        for (int mt = 0; mt < 2; mt++) {
            const int r = bm + warpM * 32 + mt * 16 + (lane >> 2);
            float2 o0 = {acc[mt][nt][0] + bbias.x, acc[mt][nt][1] + bbias.y};
            float2 o1 = {acc[mt][nt][2] + bbias.x, acc[mt][nt][3] + bbias.y};
            *(float2*)&g_proj[(size_t)r * ODIM + c] = o0;
            *(float2*)&g_proj[(size_t)(r + 8) * ODIM + c] = o1;
        }
    }
}

// ---------------- window attention ----------------
__global__ __launch_bounds__(256) void window_kernel(const float* __restrict__ ln_w,
                                                     const float* __restrict__ ln_b,
                                                     float* __restrict__ out) {
    const int hh = blockIdx.x;
    const int n = blockIdx.y;
    __shared__ float s_sc[160];
    __shared__ float s_w[28][25];
    __shared__ __align__(16) float ps[5][32][68];

    const int tid = threadIdx.x;
    if (tid < 160)
        s_sc[tid] = g_score[(size_t)(n * 32 + hh + (tid >> 5)) * 32 + (tid & 31)];
    __syncthreads();

    if (tid < 28) {
        const int ww = tid;
        float v[25];
        float mu = 0.f;
#pragma unroll
        for (int ki = 0; ki < 5; ki++)
#pragma unroll
            for (int kj = 0; kj < 5; kj++) {
                float tv = s_sc[ki * 32 + ww + kj];
                v[ki * 5 + kj] = tv;
                mu += tv;
            }
        mu *= (1.f / 25.f);
        float var = 0.f;
#pragma unroll
        for (int k = 0; k < 25; k++) {
            float d = v[k] - mu;
            var += d * d;
        }
        var *= (1.f / 25.f);
        float inv = rsqrtf(var + 1e-5f);
        float mx = -1e30f;
#pragma unroll
        for (int k = 0; k < 25; k++) {
            v[k] = (v[k] - mu) * inv * ln_w[k] + ln_b[k];
            mx = fmaxf(mx, v[k]);
        }
        float s = 0.f;
#pragma unroll
        for (int k = 0; k < 25; k++) {
            v[k] = __expf(v[k] - mx);
            s += v[k];
        }
        float r = 1.f / s;
#pragma unroll
        for (int k = 0; k < 25; k++) s_w[ww][k] = v[k] * r;
    }
    __syncthreads();

    const int ww = tid & 31;
    const int cq = tid >> 5;
    const bool act = (ww < HH);
    float wt[25];
    const int wsrc = act ? ww : 0;
#pragma unroll
    for (int k = 0; k < 25; k++) wt[k] = s_w[wsrc][k];

    for (int c0 = 0; c0 < ODIM; c0 += 64) {
        __syncthreads();
        for (int i = tid; i < 2560; i += 256) {
            int pos = i >> 4;
            int q = i & 15;
            int ki = pos >> 5, w = pos & 31;
            *(float4*)&ps[ki][w][q << 2] =
                *(const float4*)&g_proj[(size_t)((n * 32 + hh + ki) * 32 + w) * ODIM + c0 + (q << 2)];
        }
        __syncthreads();
        if (act) {
#pragma unroll
            for (int rep = 0; rep < 2; rep++) {
                int cq4 = cq + rep * 8;
                float4 acc = {0.f, 0.f, 0.f, 0.f};
#pragma unroll
                for (int ki = 0; ki < 5; ki++)
#pragma unroll
                    for (int kj = 0; kj < 5; kj++) {
                        float wv = wt[ki * 5 + kj];
                        float4 p = *(const float4*)&ps[ki][ww + kj][cq4 << 2];
                        acc.x = fmaf(wv, p.x, acc.x);
                        acc.y = fmaf(wv, p.y, acc.y);
                        acc.z = fmaf(wv, p.z, acc.z);
                        acc.w = fmaf(wv, p.w, acc.w);
                    }
                int c = c0 + (cq4 << 2);
                size_t ob = ((size_t)(n * 512 + c) * HH + hh) * HH + ww;
                out[ob] = acc.x;
                out[ob + 784] = acc.y;
                out[ob + 1568] = acc.z;
                out[ob + 2352] = acc.w;
            }
        }
    }
}

extern "C" void kernel_launch(void* const* d_in, const int* in_sizes, int n_in,
                              void* d_out, int out_size) {
    const float* x       = (const float*)d_in[0];
    const float* proj_w  = (const float*)d_in[1];
    const float* proj_b  = (const float*)d_in[2];
    const float* score_w = (const float*)d_in[3];
    const float* score_b = (const float*)d_in[4];
    const float* ln_w    = (const float*)d_in[5];
    const float* ln_b    = (const float*)d_in[6];
    float* out = (float*)d_out;

    convert_kernel<<<1088, 256>>>(x, proj_w, score_w, score_b);
    gemm_mma<<<dim3(4, 64), 256>>>(proj_b);
    window_kernel<<<dim3(HH, 8), 256>>>(ln_w, ln_b, out);
}

// round 6
// speedup vs baseline: 2.7299x; 1.2417x over previous
#include <cuda_runtime.h>
#include <cuda_fp16.h>
#include <cstdint>

// x: (8,512,32,32) fp32 == xr[8192][512]; proj_w (512,512); proj_b (512)
// score_w (512); score_b (1); ln_w (25); ln_b (25); out (8,512,28,28) fp32

#define M_ROWS 8192
#define KDIM   512
#define ODIM   512
#define HH     28

// ---------------- scratch ----------------
__device__ float g_proj[M_ROWS * ODIM];     // 16 MB
__device__ float g_score[M_ROWS];
__device__ __half g_A[M_ROWS * KDIM];       // 8 MB   (fp16(x))
__device__ __half g_W[ODIM * KDIM];         // 0.5 MB (fp16(w))

// ---------------- helpers ----------------
__device__ __forceinline__ uint32_t smem_u32(const void* p) {
    uint32_t a;
    asm("{ .reg .u64 t; cvta.to.shared.u64 t, %1; cvt.u32.u64 %0, t; }" : "=r"(a) : "l"(p));
    return a;
}
__device__ __forceinline__ void cp_async16(uint32_t sa, const void* ga) {
    asm volatile("cp.async.cg.shared.global [%0], [%1], 16;" :: "r"(sa), "l"(ga) : "memory");
}
__device__ __forceinline__ void cp_commit() {
    asm volatile("cp.async.commit_group;" ::: "memory");
}
__device__ __forceinline__ void cp_wait1() {
    asm volatile("cp.async.wait_group 1;" ::: "memory");
}
__device__ __forceinline__ void ldsm4(uint32_t* r, uint32_t a) {
    asm volatile("ldmatrix.sync.aligned.m8n8.x4.shared.b16 {%0,%1,%2,%3}, [%4];"
                 : "=r"(r[0]), "=r"(r[1]), "=r"(r[2]), "=r"(r[3]) : "r"(a));
}
__device__ __forceinline__ void mma_f16(float* c, const uint32_t* a, const uint32_t* b) {
    asm volatile(
        "mma.sync.aligned.m16n8k16.row.col.f32.f16.f16.f32 "
        "{%0,%1,%2,%3}, {%4,%5,%6,%7}, {%8,%9}, {%0,%1,%2,%3};"
        : "+f"(c[0]), "+f"(c[1]), "+f"(c[2]), "+f"(c[3])
        : "r"(a[0]), "r"(a[1]), "r"(a[2]), "r"(a[3]), "r"(b[0]), "r"(b[1]));
}

// ---------------- convert + score (single pass, MLP 4) ----------------
__global__ __launch_bounds__(256) void convert_kernel(const float* __restrict__ x,
                                                      const float* __restrict__ pw,
                                                      const float* __restrict__ sw,
                                                      const float* __restrict__ sb) {
    const int row = blockIdx.x * 8 + (threadIdx.x >> 5);
    const int lane = threadIdx.x & 31;
    const bool isX = row < M_ROWS;
    const float4* src = (const float4*)(isX ? x + (size_t)row * KDIM
                                            : pw + (size_t)(row - M_ROWS) * KDIM);
    float4 v0 = src[2 * lane];
    float4 v1 = src[2 * lane + 1];
    float4 v2 = src[2 * lane + 64];
    float4 v3 = src[2 * lane + 65];

    __half2 h0 = __floats2half2_rn(v0.x, v0.y), h1 = __floats2half2_rn(v0.z, v0.w);
    __half2 h2 = __floats2half2_rn(v1.x, v1.y), h3 = __floats2half2_rn(v1.z, v1.w);
    __half2 h4 = __floats2half2_rn(v2.x, v2.y), h5 = __floats2half2_rn(v2.z, v2.w);
    __half2 h6 = __floats2half2_rn(v3.x, v3.y), h7 = __floats2half2_rn(v3.z, v3.w);
    uint4 ua, ub;
    ua.x = *(uint32_t*)&h0; ua.y = *(uint32_t*)&h1; ua.z = *(uint32_t*)&h2; ua.w = *(uint32_t*)&h3;
    ub.x = *(uint32_t*)&h4; ub.y = *(uint32_t*)&h5; ub.z = *(uint32_t*)&h6; ub.w = *(uint32_t*)&h7;

    if (isX) {
        uint4* dst = (uint4*)(g_A + (size_t)row * KDIM);
        dst[lane] = ua;
        dst[lane + 32] = ub;
        const float4* w4 = (const float4*)sw;
        float4 w0 = w4[2 * lane], w1 = w4[2 * lane + 1];
        float4 w2 = w4[2 * lane + 64], w3 = w4[2 * lane + 65];
        float acc = v0.x * w0.x + v0.y * w0.y + v0.z * w0.z + v0.w * w0.w;
        acc += v1.x * w1.x + v1.y * w1.y + v1.z * w1.z + v1.w * w1.w;
        acc += v2.x * w2.x + v2.y * w2.y + v2.z * w2.z + v2.w * w2.w;
        acc += v3.x * w3.x + v3.y * w3.y + v3.z * w3.z + v3.w * w3.w;
#pragma unroll
        for (int off = 16; off; off >>= 1) acc += __shfl_xor_sync(0xffffffffu, acc, off);
        if (lane == 0) g_score[row] = acc + sb[0];
    } else {
        const int wr = row - M_ROWS;
        uint4* dh = (uint4*)(g_W + (size_t)wr * KDIM);
        dh[lane] = ua;
        dh[lane + 32] = ub;
    }
}

// ---------------- HMMA GEMM (fp16 x fp16, f32 accum, k-chunk 32, 2-stage) ----------------
// CTA 128x128, 8 warps (4M x 2N). Stage: A(8KB) + W(8KB) = 16KB. 2 stages = 32KB.
// Rows are 64B (32 halfs); swizzle: 16B quad q at row r -> q ^ ((r>>1)&3).
#define RGN     8192
#define STAGEB  (2 * RGN)
#define NIT     16

__device__ __forceinline__ uint32_t swz64(int r, int q) {
    return (uint32_t)(r * 64 + ((q ^ ((r >> 1) & 3)) << 4));
}

__global__ __launch_bounds__(256, 2) void gemm_mma(const float* __restrict__ bias) {
    __shared__ __align__(16) char smem[2 * STAGEB];   // 32KB
    const int tid = threadIdx.x;
    const int lane = tid & 31;
    const int wid = tid >> 5;
    const int warpM = wid >> 1;
    const int warpN = wid & 1;
    const int bm = blockIdx.y * 128;
    const int bn = blockIdx.x * 128;
    const uint32_t sbase = smem_u32(smem);

    // loader: 1024 16B-chunks / 256 threads = 4 per thread
    uint32_t ldst[4];
    const __half* lsrc[4];
#pragma unroll
    for (int i = 0; i < 4; i++) {
        int c = tid + 256 * i;
        int region = c >> 9;          // 0:A 1:W
        int r = (c & 511) >> 2;
        int q = c & 3;
        ldst[i] = sbase + region * RGN + swz64(r, q);
        const __half* base = (region == 0) ? g_A + (size_t)(bm + r) * KDIM
                                           : g_W + (size_t)(bn + r) * KDIM;
        lsrc[i] = base + q * 8;
    }

    // fragment address components
    const int t = lane >> 3;
    const int arow0 = warpM * 32 + (t & 1) * 8 + (lane & 7);
    const int brow = warpN * 64 + (t >> 1) * 8 + (lane & 7);
    const int aq = t >> 1;
    const int bq = t & 1;

    float acc[2][8][4];
#pragma unroll
    for (int i = 0; i < 2; i++)
#pragma unroll
        for (int j = 0; j < 8; j++)
#pragma unroll
            for (int q = 0; q < 4; q++) acc[i][j][q] = 0.f;

    // prologue: stages 0,1
#pragma unroll
    for (int s = 0; s < 2; s++) {
#pragma unroll
        for (int i = 0; i < 4; i++) cp_async16(ldst[i] + s * STAGEB, lsrc[i] + s * 32);
        cp_commit();
    }

    for (int it = 0; it < NIT; it++) {
        cp_wait1();
        __syncthreads();
        const uint32_t stb = sbase + (it & 1) * STAGEB;

#pragma unroll
        for (int kk = 0; kk < 2; kk++) {
            uint32_t ah[2][4], bb[2][2][4];
            ldsm4(ah[0], stb + swz64(arow0, kk * 2 + aq));
            ldsm4(ah[1], stb + swz64(arow0 + 16, kk * 2 + aq));
            ldsm4(bb[0][0], stb + RGN + swz64(brow, kk * 2 + bq));
            ldsm4(bb[0][1], stb + RGN + swz64(brow + 16, kk * 2 + bq));
            ldsm4(bb[1][0], stb + RGN + swz64(brow + 32, kk * 2 + bq));
            ldsm4(bb[1][1], stb + RGN + swz64(brow + 48, kk * 2 + bq));
            if (kk == 1) {
                __syncthreads();   // all warps done reading this stage
                if (it + 2 < NIT) {
#pragma unroll
                    for (int i = 0; i < 4; i++)
                        cp_async16(ldst[i] + (it & 1) * STAGEB, lsrc[i] + (it + 2) * 32);
                }
                cp_commit();
            }
#pragma unroll
            for (int h = 0; h < 2; h++)
#pragma unroll
                for (int mt = 0; mt < 2; mt++)
#pragma unroll
                    for (int ntl = 0; ntl < 4; ntl++)
                        mma_f16(acc[mt][h * 4 + ntl], ah[mt], &bb[h][ntl >> 1][(ntl & 1) * 2]);
        }
    }

    // epilogue
#pragma unroll
    for (int nt = 0; nt < 8; nt++) {
        const int c = bn + warpN * 64 + nt * 8 + (lane & 3) * 2;
        float2 bbias = *(const float2*)&bias[c];
#pragma unroll
        for (int mt = 0; mt < 2; mt++) {
            const int r = bm + warpM * 32 + mt * 16 + (lane >> 2);
            float2 o0 = {acc[mt][nt][0] + bbias.x, acc[mt][nt][1] + bbias.y};
            float2 o1 = {acc[mt][nt][2] + bbias.x, acc[mt][nt][3] + bbias.y};
            *(float2*)&g_proj[(size_t)r * ODIM + c] = o0;
            *(float2*)&g_proj[(size_t)(r + 8) * ODIM + c] = o1;
        }
    }
}

// ---------------- window attention ----------------
__global__ __launch_bounds__(256) void window_kernel(const float* __restrict__ ln_w,
                                                     const float* __restrict__ ln_b,
                                                     float* __restrict__ out) {
    const int hh = blockIdx.x;
    const int n = blockIdx.y;
    __shared__ float s_sc[160];
    __shared__ float s_w[28][25];
    __shared__ __align__(16) float ps[5][32][68];

    const int tid = threadIdx.x;
    if (tid < 160)
        s_sc[tid] = g_score[(size_t)(n * 32 + hh + (tid >> 5)) * 32 + (tid & 31)];
    __syncthreads();

    if (tid < 28) {
        const int ww = tid;
        float v[25];
        float mu = 0.f;
#pragma unroll
        for (int ki = 0; ki < 5; ki++)
#pragma unroll
            for (int kj = 0; kj < 5; kj++) {
                float tv = s_sc[ki * 32 + ww + kj];
                v[ki * 5 + kj] = tv;
                mu += tv;
            }
        mu *= (1.f / 25.f);
        float var = 0.f;
#pragma unroll
        for (int k = 0; k < 25; k++) {
            float d = v[k] - mu;
            var += d * d;
        }
        var *= (1.f / 25.f);
        float inv = rsqrtf(var + 1e-5f);
        float mx = -1e30f;
#pragma unroll
        for (int k = 0; k < 25; k++) {
            v[k] = (v[k] - mu) * inv * ln_w[k] + ln_b[k];
            mx = fmaxf(mx, v[k]);
        }
        float s = 0.f;
#pragma unroll
        for (int k = 0; k < 25; k++) {
            v[k] = __expf(v[k] - mx);
            s += v[k];
        }
        float r = 1.f / s;
#pragma unroll
        for (int k = 0; k < 25; k++) s_w[ww][k] = v[k] * r;
    }
    __syncthreads();

    const int ww = tid & 31;
    const int cq = tid >> 5;
    const bool act = (ww < HH);
    float wt[25];
    const int wsrc = act ? ww : 0;
#pragma unroll
    for (int k = 0; k < 25; k++) wt[k] = s_w[wsrc][k];

    for (int c0 = 0; c0 < ODIM; c0 += 64) {
        __syncthreads();
        for (int i = tid; i < 2560; i += 256) {
            int pos = i >> 4;
            int q = i & 15;
            int ki = pos >> 5, w = pos & 31;
            *(float4*)&ps[ki][w][q << 2] =
                *(const float4*)&g_proj[(size_t)((n * 32 + hh + ki) * 32 + w) * ODIM + c0 + (q << 2)];
        }
        __syncthreads();
        if (act) {
#pragma unroll
            for (int rep = 0; rep < 2; rep++) {
                int cq4 = cq + rep * 8;
                float4 acc = {0.f, 0.f, 0.f, 0.f};
#pragma unroll
                for (int ki = 0; ki < 5; ki++)
#pragma unroll
                    for (int kj = 0; kj < 5; kj++) {
                        float wv = wt[ki * 5 + kj];
                        float4 p = *(const float4*)&ps[ki][ww + kj][cq4 << 2];
                        acc.x = fmaf(wv, p.x, acc.x);
                        acc.y = fmaf(wv, p.y, acc.y);
                        acc.z = fmaf(wv, p.z, acc.z);
                        acc.w = fmaf(wv, p.w, acc.w);
                    }
                int c = c0 + (cq4 << 2);
                size_t ob = ((size_t)(n * 512 + c) * HH + hh) * HH + ww;
                out[ob] = acc.x;
                out[ob + 784] = acc.y;
                out[ob + 1568] = acc.z;
                out[ob + 2352] = acc.w;
            }
        }
    }
}

extern "C" void kernel_launch(void* const* d_in, const int* in_sizes, int n_in,
                              void* d_out, int out_size) {
    const float* x       = (const float*)d_in[0];
    const float* proj_w  = (const float*)d_in[1];
    const float* proj_b  = (const float*)d_in[2];
    const float* score_w = (const float*)d_in[3];
    const float* score_b = (const float*)d_in[4];
    const float* ln_w    = (const float*)d_in[5];
    const float* ln_b    = (const float*)d_in[6];
    float* out = (float*)d_out;

    convert_kernel<<<1088, 256>>>(x, proj_w, score_w, score_b);
    gemm_mma<<<dim3(4, 64), 256>>>(proj_b);
    window_kernel<<<dim3(HH, 8), 256>>>(ln_w, ln_b, out);
}